// round 7
// baseline (speedup 1.0000x reference)
#include <cuda_runtime.h>
#include <math.h>

#define H 64
#define W 64
#define C 256
#define P 7
#define NUM_ROIS 256
#define FC (W * C)   // floats per x-row (16384)

__device__ __forceinline__ float4 fmax4(float4 a, float4 b) {
    a.x = fmaxf(a.x, b.x);
    a.y = fmaxf(a.y, b.y);
    a.z = fmaxf(a.z, b.z);
    a.w = fmaxf(a.w, b.w);
    return a;
}

// Block = (roi, i), 224 threads = 7 warps; warp j computes y-bin j.
// Bin bounds computed once per block into smem (threads 0-6: y-bins,
// thread 7: x-bin). Inner loop: 2 x-rows x 2 y x 2 channel-chunks = 8
// immediate-offset loads per iteration (row/tail clamps are max-safe L1 hits).
__global__ __launch_bounds__(224, 6) void roi_pool_kernel(
    const float* __restrict__ feat,   // (H, W, C)
    const float* __restrict__ rois,   // (NUM_ROIS, 4) = x1,y1,x2,y2
    float* __restrict__ out)          // (NUM_ROIS, P, P, C)
{
    __shared__ int s_ys[P], s_ylen[P], s_xs, s_xlen;

    const int b = blockIdx.x;         // r*P + i
    const int r = b / P;
    const int i = b - r * P;

    const int tid  = (int)threadIdx.x;
    const int j    = tid >> 5;        // warp id = y-bin (0..6)
    const int lane = tid & 31;
    const int c0   = lane << 2;       // first channel quad (second at +128)

    if (tid < 8) {
        if (tid < P) {
            // y (W) bin bounds for bin tid — exact reference math
            const float y1 = __ldg(&rois[r * 4 + 1]);
            const float y2 = __ldg(&rois[r * 4 + 3]);
            const int loy   = (int)floorf(y1 * (float)W);
            const int hiy   = (int)ceilf(y2 * (float)W);
            const int spany = max(hiy - loy, 1);
            const int ys    = loy + (tid * spany) / P;
            const int ye    = loy + ((tid + 1) * spany + (P - 1)) / P;
            s_ys[tid]   = ys;
            s_ylen[tid] = max(ye - ys, 1);
        } else {
            // x (H) bin bounds for this block's i
            const float x1 = __ldg(&rois[r * 4 + 0]);
            const float x2 = __ldg(&rois[r * 4 + 2]);
            const int lox   = (int)floorf(x1 * (float)H);
            const int hix   = (int)ceilf(x2 * (float)H);
            const int spanx = max(hix - lox, 1);
            const int xs    = lox + (i * spanx) / P;
            const int xe    = lox + ((i + 1) * spanx + (P - 1)) / P;
            s_xs   = xs;
            s_xlen = max(xe - xs, 1);
        }
    }
    __syncthreads();

    const int xs     = s_xs;
    const int xlen   = s_xlen;
    const int ys     = s_ys[j];
    const int ylen   = s_ylen[j];
    const int npairs = ylen >> 1;
    const bool ytail = (ylen & 1) != 0;
    const int  tailo = (npairs * 2) * C;

    const float NEG = -INFINITY;
    float4 aL = make_float4(NEG, NEG, NEG, NEG);
    float4 aH = aL;

    const float* rowp = feat + (size_t)xs * FC + (size_t)ys * C + c0;

    for (int sx = 0; sx < xlen; sx += 2) {
        // second row clamped to this row when past the end (dup = L1 hit)
        const int rstep = (sx + 1 < xlen) ? FC : 0;
        const float* p0 = rowp;
        const float* p1 = rowp + rstep;
        for (int sp = 0; sp < npairs; ++sp) {
            // 8 independent loads, immediate offsets off 2 base pointers
            const float4 vL0 = *reinterpret_cast<const float4*>(p0);
            const float4 vH0 = *reinterpret_cast<const float4*>(p0 + 128);
            const float4 vL1 = *reinterpret_cast<const float4*>(p0 + C);
            const float4 vH1 = *reinterpret_cast<const float4*>(p0 + C + 128);
            const float4 wL0 = *reinterpret_cast<const float4*>(p1);
            const float4 wH0 = *reinterpret_cast<const float4*>(p1 + 128);
            const float4 wL1 = *reinterpret_cast<const float4*>(p1 + C);
            const float4 wH1 = *reinterpret_cast<const float4*>(p1 + C + 128);
            aL = fmax4(aL, fmax4(vL0, vL1));
            aH = fmax4(aH, fmax4(vH0, vH1));
            aL = fmax4(aL, fmax4(wL0, wL1));
            aH = fmax4(aH, fmax4(wH0, wH1));
            p0 += 2 * C;
            p1 += 2 * C;
        }
        if (ytail) {   // warp-uniform odd-y tail: one y, both rows
            const float* t0 = rowp + tailo;
            const float* t1 = rowp + tailo + rstep;
            const float4 vL = *reinterpret_cast<const float4*>(t0);
            const float4 vH = *reinterpret_cast<const float4*>(t0 + 128);
            const float4 wL = *reinterpret_cast<const float4*>(t1);
            const float4 wH = *reinterpret_cast<const float4*>(t1 + 128);
            aL = fmax4(aL, fmax4(vL, wL));
            aH = fmax4(aH, fmax4(vH, wH));
        }
        rowp += 2 * FC;
    }

    float* op = out + (((size_t)(r * P + i) * P + j) * C) + c0;
    *reinterpret_cast<float4*>(op)       = aL;
    *reinterpret_cast<float4*>(op + 128) = aH;
}

extern "C" void kernel_launch(void* const* d_in, const int* in_sizes, int n_in,
                              void* d_out, int out_size) {
    const float* feat = (const float*)d_in[0];
    const float* rois = (const float*)d_in[1];
    if (n_in >= 2 && in_sizes[0] == NUM_ROIS * 4 && in_sizes[1] == H * W * C) {
        feat = (const float*)d_in[1];
        rois = (const float*)d_in[0];
    }
    float* out = (float*)d_out;

    roi_pool_kernel<<<NUM_ROIS * P, 224>>>(feat, rois, out);
}

// round 8
// speedup vs baseline: 1.4507x; 1.4507x over previous
#include <cuda_runtime.h>
#include <math.h>

#define H 64
#define W 64
#define C 256
#define P 7
#define NUM_ROIS 256
#define FC (W * C)   // floats per x-row (16384)

__device__ __forceinline__ float4 fmax4(float4 a, float4 b) {
    a.x = fmaxf(a.x, b.x);
    a.y = fmaxf(a.y, b.y);
    a.z = fmaxf(a.z, b.z);
    a.w = fmaxf(a.w, b.w);
    return a;
}

// One block per (roi, i, j) bin; 64 threads = 64 float4 channel groups.
// 12544 small blocks -> fine-grained SM load balance. y-loop: ylen/2 clean
// pairs + warp-uniform odd tail => zero duplicate loads. Low regs => block
// count-limited occupancy (up to 32 CTAs/SM).
__global__ __launch_bounds__(64) void roi_pool_kernel(
    const float* __restrict__ feat,   // (H, W, C)
    const float* __restrict__ rois,   // (NUM_ROIS, 4) = x1,y1,x2,y2
    float* __restrict__ out)          // (NUM_ROIS, P, P, C)
{
    const int b  = blockIdx.x;        // r*49 + i*7 + j
    const int r  = b / (P * P);
    const int ij = b - r * (P * P);
    const int i  = ij / P;
    const int j  = ij - i * P;

    const int c4 = (int)threadIdx.x << 2;   // channel quad

    const float x1 = __ldg(&rois[r * 4 + 0]);
    const float y1 = __ldg(&rois[r * 4 + 1]);
    const float x2 = __ldg(&rois[r * 4 + 2]);
    const float y2 = __ldg(&rois[r * 4 + 3]);

    // x (H) bin bounds — exact reference math; in-range for 0<=x1<x2<=1.
    const int lox   = (int)floorf(x1 * (float)H);
    const int hix   = (int)ceilf(x2 * (float)H);
    const int spanx = max(hix - lox, 1);
    const int xs    = lox + (i * spanx) / P;
    const int xe    = lox + ((i + 1) * spanx + (P - 1)) / P;
    const int xlen  = max(xe - xs, 1);

    // y (W) bin bounds.
    const int loy   = (int)floorf(y1 * (float)W);
    const int hiy   = (int)ceilf(y2 * (float)W);
    const int spany = max(hiy - loy, 1);
    const int ys    = loy + (j * spany) / P;
    const int ye    = loy + ((j + 1) * spany + (P - 1)) / P;
    const int ylen  = max(ye - ys, 1);

    const int  npairs = ylen >> 1;
    const bool ytail  = (ylen & 1) != 0;
    const int  tailo  = (npairs * 2) * C;

    const float NEG = -INFINITY;
    float4 acc = make_float4(NEG, NEG, NEG, NEG);

    const float* rowp = feat + (size_t)xs * FC + (size_t)ys * C + c4;

    for (int sx = 0; sx < xlen; ++sx) {
        const float* p = rowp;
        for (int sp = 0; sp < npairs; ++sp) {
            const float4 v0 = *reinterpret_cast<const float4*>(p);
            const float4 v1 = *reinterpret_cast<const float4*>(p + C);
            acc = fmax4(acc, fmax4(v0, v1));
            p += 2 * C;
        }
        if (ytail) {   // warp-uniform: single real tail element, no dup
            acc = fmax4(acc, *reinterpret_cast<const float4*>(rowp + tailo));
        }
        rowp += FC;
    }

    float* op = out + ((size_t)b * C) + c4;
    *reinterpret_cast<float4*>(op) = acc;
}

extern "C" void kernel_launch(void* const* d_in, const int* in_sizes, int n_in,
                              void* d_out, int out_size) {
    const float* feat = (const float*)d_in[0];
    const float* rois = (const float*)d_in[1];
    if (n_in >= 2 && in_sizes[0] == NUM_ROIS * 4 && in_sizes[1] == H * W * C) {
        feat = (const float*)d_in[1];
        rois = (const float*)d_in[0];
    }
    float* out = (float*)d_out;

    roi_pool_kernel<<<NUM_ROIS * P * P, 64>>>(feat, rois, out);
}